// round 3
// baseline (speedup 1.0000x reference)
#include <cuda_runtime.h>
#include <cuda_fp16.h>
#include <cstdint>
#include <cstddef>

// ===================== problem constants =====================
static constexpr int NB   = 8192;               // batch
static constexpr int NIN  = 1024;               // in features
static constexpr int NOUT = 1024;               // out features
static constexpr int COEF = 8;                  // grid_size + spline_order
static constexpr int NK   = NIN + NIN * COEF;   // 9216 fused K

// ===================== gemm tiling =====================
static constexpr int BM = 128;
static constexpr int BN = 128;
static constexpr int BK = 64;                   // 64 fp16 = 128B rows in smem
static constexpr int KTILES = NK / BK;          // 144
static constexpr int STAGES = 4;

static constexpr uint32_t TILE_BYTES = (uint32_t)BM * BK * 2;   // 16384 (A == B size)
static constexpr uint32_t SMEM_TOTAL = 2 * STAGES * TILE_BYTES; // 131072

// ===================== device scratch (no allocations allowed) =====================
__device__ __align__(1024) __half g_Ah[(size_t)NB * NK];     // ~151 MB fp16 activations
__device__ __align__(1024) __half g_Wh[(size_t)NOUT * NK];   // ~19 MB fp16 packed weights

// ===================== helpers =====================
__device__ __forceinline__ uint32_t smem_u32(const void* p) {
    uint32_t a;
    asm("{ .reg .u64 t; cvta.to.shared.u64 t, %1; cvt.u32.u64 %0, t; }" : "=r"(a) : "l"(p));
    return a;
}
__device__ __forceinline__ void cp16(uint32_t dst, const void* src) {
    asm volatile("cp.async.cg.shared.global [%0], [%1], 16;" :: "r"(dst), "l"(src) : "memory");
}
#define CP_COMMIT() asm volatile("cp.async.commit_group;" ::: "memory")
#define CP_WAIT2()  asm volatile("cp.async.wait_group 2;" ::: "memory")

__device__ __forceinline__ void ldmx4(uint32_t& r0, uint32_t& r1, uint32_t& r2, uint32_t& r3,
                                      uint32_t addr) {
    asm volatile("ldmatrix.sync.aligned.m8n8.x4.shared.b16 {%0,%1,%2,%3}, [%4];"
                 : "=r"(r0), "=r"(r1), "=r"(r2), "=r"(r3) : "r"(addr));
}
__device__ __forceinline__ void mma16816(float& c0, float& c1, float& c2, float& c3,
                                         uint32_t a0, uint32_t a1, uint32_t a2, uint32_t a3,
                                         uint32_t b0, uint32_t b1) {
    asm volatile(
        "mma.sync.aligned.m16n8k16.row.col.f32.f16.f16.f32 "
        "{%0,%1,%2,%3}, {%4,%5,%6,%7}, {%8,%9}, {%0,%1,%2,%3};"
        : "+f"(c0), "+f"(c1), "+f"(c2), "+f"(c3)
        : "r"(a0), "r"(a1), "r"(a2), "r"(a3), "r"(b0), "r"(b1));
}

// ===================== kernel 1: pack weights to fp16 =====================
// g_Wh[o, 0:1024] = base_weight[o,:]; g_Wh[o, 1024 + i*8 + g] = spline_weight[o,i,g]
__global__ void kan_wpack(const float* __restrict__ bw, const float* __restrict__ sw) {
    constexpr int HK = NK / 2;                       // 4608 fp16-pairs per output row
    int p = blockIdx.x * blockDim.x + threadIdx.x;   // exact grid
    int o  = p / HK;
    int r  = p - o * HK;
    int kk = r * 2;
    float2 f;
    if (kk < NIN)
        f = *reinterpret_cast<const float2*>(bw + (size_t)o * NIN + kk);
    else
        f = *reinterpret_cast<const float2*>(sw + (size_t)o * (NIN * COEF) + (kk - NIN));
    reinterpret_cast<__half2*>(g_Wh + (size_t)o * NK)[r] = __floats2half2_rn(f.x, f.y);
}

// ===================== kernel 2: activations (silu + cubic B-spline bases) =====================
__global__ void kan_act(const float* __restrict__ x) {
    int idx = blockIdx.x * blockDim.x + threadIdx.x;   // exact grid
    int b = idx >> 10;
    int i = idx & (NIN - 1);
    float v = x[idx];
    size_t ro = (size_t)b * NK;

    // silu
    float s = v / (1.0f + __expf(-v));
    g_Ah[ro + i] = __float2half_rn(s);

    // uniform cubic B-spline on knots (i-3)/5: interval j = floor(5x) in [0,4], t in [0,1)
    float xs = v * 5.0f;
    int j = (int)floorf(xs);
    j = (j < 0) ? 0 : ((j > 4) ? 4 : j);
    float t = xs - (float)j;
    float t2 = t * t, t3 = t2 * t, omt = 1.0f - t;
    float n0 = omt * omt * omt * (1.0f / 6.0f);
    float n1 = (3.0f * t3 - 6.0f * t2 + 4.0f) * (1.0f / 6.0f);
    float n2 = (-3.0f * t3 + 3.0f * t2 + 3.0f * t + 1.0f) * (1.0f / 6.0f);
    float n3 = t3 * (1.0f / 6.0f);

    __half h[8];
#pragma unroll
    for (int g = 0; g < 8; ++g) {
        float val = (g == j) ? n0 : (g == j + 1) ? n1 : (g == j + 2) ? n2
                  : (g == j + 3) ? n3 : 0.0f;
        h[g] = __float2half_rn(val);
    }
    __half2 p0 = __halves2half2(h[0], h[1]);
    __half2 p1 = __halves2half2(h[2], h[3]);
    __half2 p2 = __halves2half2(h[4], h[5]);
    __half2 p3 = __halves2half2(h[6], h[7]);
    uint4 u;
    u.x = *reinterpret_cast<uint32_t*>(&p0);
    u.y = *reinterpret_cast<uint32_t*>(&p1);
    u.z = *reinterpret_cast<uint32_t*>(&p2);
    u.w = *reinterpret_cast<uint32_t*>(&p3);
    *reinterpret_cast<uint4*>(g_Ah + ro + NIN + (size_t)i * 8) = u;  // 16B aligned
}

// ===================== kernel 3: pipelined HMMA GEMM =====================
// out[m,n] = sum_k A[m,k] * W[n,k].  A row-major, W acts as col-major B.
// smem tile layout: 128 rows x 64 halves (=8 chunks of 16B), chunk swizzle: phys = c ^ (row&7)
__global__ void __launch_bounds__(256, 1) kan_gemm(float* __restrict__ out) {
    extern __shared__ __align__(1024) char smem[];
    const uint32_t sb = smem_u32(smem);
    const uint32_t sbA = sb;
    const uint32_t sbB = sb + STAGES * TILE_BYTES;

    const int tid = threadIdx.x;
    const int lane = tid & 31;
    const int wid = tid >> 5;
    const int wm = wid & 3;          // 4 warps along M
    const int wn = wid >> 2;         // 2 warps along N

    const int ntile = blockIdx.x & 7;         // n fastest: A-tile L2 reuse
    const int mtile = blockIdx.x >> 3;
    const int m0 = mtile * BM;
    const int n0 = ntile * BN;

    // ---- per-thread cp.async source/dest (4 chunks of 16B for A, 4 for B per stage) ----
    // chunk c in [0,1024): row = c>>3, col = c&7 ; dst chunk = col ^ (row&7)
    const char* gA = (const char*)(g_Ah) + ((size_t)m0 * NK) * 2;
    const char* gB = (const char*)(g_Wh) + ((size_t)n0 * NK) * 2;

    auto load_stage = [&](int s, int kt) {
        const uint32_t dA = sbA + (uint32_t)s * TILE_BYTES;
        const uint32_t dB = sbB + (uint32_t)s * TILE_BYTES;
        const size_t koff = (size_t)kt * BK * 2;
#pragma unroll
        for (int i = 0; i < 4; ++i) {
            int c = tid + i * 256;
            int row = c >> 3, col = c & 7;
            uint32_t doff = ((uint32_t)(row << 3) + (uint32_t)(col ^ (row & 7))) << 4;
            size_t goff = (size_t)row * (NK * 2) + koff + (size_t)col * 16;
            cp16(dA + doff, gA + goff);
            cp16(dB + doff, gB + goff);
        }
    };

    // ---- prologue: fill STAGES-1 stages ----
#pragma unroll
    for (int s = 0; s < STAGES - 1; ++s) { load_stage(s, s); CP_COMMIT(); }

    float acc[2][8][4];
#pragma unroll
    for (int mi = 0; mi < 2; ++mi)
#pragma unroll
        for (int ni = 0; ni < 8; ++ni)
#pragma unroll
            for (int r = 0; r < 4; ++r) acc[mi][ni][r] = 0.0f;

    // ---- precompute ldmatrix row bases ----
    // A lanes: row = wm*32 + mi*16 + (lane&15), k-chunk = ks*2 + (lane>>4)
    // B lanes: row = wn*64 + g*16 + (lane&7) + ((lane>>4)<<3), k-chunk = ks*2 + ((lane>>3)&1)
    const int arow = wm * 32 + (lane & 15);
    const int brow = wn * 64 + (lane & 7) + ((lane >> 4) << 3);
    const uint32_t aRowOff = (uint32_t)arow << 7;      // row*128B
    const uint32_t aPar = (uint32_t)(arow & 7);
    const uint32_t aKsel = (uint32_t)(lane >> 4);
    const uint32_t bKsel = (uint32_t)((lane >> 3) & 1);

    CP_WAIT2();
    __syncthreads();

    for (int kt = 0; kt < KTILES; ++kt) {
        const int s = kt & (STAGES - 1);
        const uint32_t tA = sbA + (uint32_t)s * TILE_BYTES;
        const uint32_t tB = sbB + (uint32_t)s * TILE_BYTES;

#pragma unroll
        for (int ks = 0; ks < 4; ++ks) {
            // A fragments: two m16 blocks
            uint32_t a[2][4];
#pragma unroll
            for (int mi = 0; mi < 2; ++mi) {
                uint32_t row = aRowOff + ((uint32_t)mi << 11);        // +16 rows = 2048B
                uint32_t chunk = ((uint32_t)(ks * 2) + aKsel) ^ aPar;
                ldmx4(a[mi][0], a[mi][1], a[mi][2], a[mi][3], tA + row + (chunk << 4));
            }
            // B fragments: four n16 groups (8 n8 tiles)
            uint32_t b[8][2];
#pragma unroll
            for (int g = 0; g < 4; ++g) {
                int r = brow + g * 16;
                uint32_t chunk = ((uint32_t)(ks * 2) + bKsel) ^ (uint32_t)(r & 7);
                uint32_t q0, q1, q2, q3;
                ldmx4(q0, q1, q2, q3, tB + ((uint32_t)r << 7) + (chunk << 4));
                b[g * 2 + 0][0] = q0; b[g * 2 + 0][1] = q1;
                b[g * 2 + 1][0] = q2; b[g * 2 + 1][1] = q3;
            }
#pragma unroll
            for (int mi = 0; mi < 2; ++mi)
#pragma unroll
                for (int ni = 0; ni < 8; ++ni)
                    mma16816(acc[mi][ni][0], acc[mi][ni][1], acc[mi][ni][2], acc[mi][ni][3],
                             a[mi][0], a[mi][1], a[mi][2], a[mi][3],
                             b[ni][0], b[ni][1]);
        }

        __syncthreads();                       // everyone done reading stage s
        if (kt + STAGES - 1 < KTILES)
            load_stage((kt + STAGES - 1) & (STAGES - 1), kt + STAGES - 1);
        CP_COMMIT();
        CP_WAIT2();                            // stage kt+1 resident
        __syncthreads();
    }

    // ---- epilogue ----
    // acc thread layout: c0:(m=q, n=p*2) c1:(q, p*2+1) c2:(q+8, p*2) c3:(q+8, p*2+1)
    const int q = lane >> 2, p = lane & 3;
#pragma unroll
    for (int mi = 0; mi < 2; ++mi) {
        int mbase = m0 + wm * 32 + mi * 16 + q;
#pragma unroll
        for (int ni = 0; ni < 8; ++ni) {
            int nbase = n0 + wn * 64 + ni * 8 + p * 2;
            float2 v0 = make_float2(acc[mi][ni][0], acc[mi][ni][1]);
            float2 v1 = make_float2(acc[mi][ni][2], acc[mi][ni][3]);
            *reinterpret_cast<float2*>(out + (size_t)mbase * NOUT + nbase) = v0;
            *reinterpret_cast<float2*>(out + (size_t)(mbase + 8) * NOUT + nbase) = v1;
        }
    }
}

// ===================== host launcher =====================
extern "C" void kernel_launch(void* const* d_in, const int* in_sizes, int n_in,
                              void* d_out, int out_size) {
    const float* x  = (const float*)d_in[0];
    const float* bw = (const float*)d_in[1];
    const float* sw = (const float*)d_in[2];
    float* out = (float*)d_out;

    cudaFuncSetAttribute(kan_gemm, cudaFuncAttributeMaxDynamicSharedMemorySize,
                         (int)SMEM_TOTAL);

    kan_wpack<<<(NOUT * (NK / 2)) / 256, 256>>>(bw, sw);
    kan_act<<<(NB * NIN) / 256, 256>>>(x);
    kan_gemm<<<(NB / BM) * (NOUT / BN), 256, SMEM_TOTAL>>>(out);
}

// round 4
// speedup vs baseline: 1.1730x; 1.1730x over previous
#include <cuda_runtime.h>
#include <cuda_fp16.h>
#include <cstdint>
#include <cstddef>

// ===================== problem constants =====================
static constexpr int NB   = 8192;               // batch
static constexpr int NIN  = 1024;               // in features
static constexpr int NOUT = 1024;               // out features
static constexpr int COEF = 8;                  // grid_size + spline_order
static constexpr int NK   = NIN + NIN * COEF;   // 9216 fused K

// ===================== gemm tiling =====================
static constexpr int BM = 256;
static constexpr int BN = 128;
static constexpr int BK = 64;                   // 64 fp16 = 128B rows in smem
static constexpr int KTILES = NK / BK;          // 144
static constexpr int STAGES = 3;

static constexpr uint32_t A_TILE = (uint32_t)BM * BK * 2;       // 32768
static constexpr uint32_t B_TILE = (uint32_t)BN * BK * 2;       // 16384
static constexpr uint32_t SMEM_TOTAL = STAGES * (A_TILE + B_TILE); // 147456

// ===================== device scratch (no allocations allowed) =====================
__device__ __align__(1024) __half g_Ah[(size_t)NB * NK];     // ~151 MB fp16 activations
__device__ __align__(1024) __half g_Wh[(size_t)NOUT * NK];   // ~19 MB fp16 packed weights

// ===================== helpers =====================
__device__ __forceinline__ uint32_t smem_u32(const void* p) {
    uint32_t a;
    asm("{ .reg .u64 t; cvta.to.shared.u64 t, %1; cvt.u32.u64 %0, t; }" : "=r"(a) : "l"(p));
    return a;
}
__device__ __forceinline__ void cp16(uint32_t dst, const void* src) {
    asm volatile("cp.async.cg.shared.global [%0], [%1], 16;" :: "r"(dst), "l"(src) : "memory");
}
#define CP_COMMIT() asm volatile("cp.async.commit_group;" ::: "memory")
#define CP_WAIT1()  asm volatile("cp.async.wait_group 1;" ::: "memory")

__device__ __forceinline__ void ldmx4(uint32_t& r0, uint32_t& r1, uint32_t& r2, uint32_t& r3,
                                      uint32_t addr) {
    asm volatile("ldmatrix.sync.aligned.m8n8.x4.shared.b16 {%0,%1,%2,%3}, [%4];"
                 : "=r"(r0), "=r"(r1), "=r"(r2), "=r"(r3) : "r"(addr));
}
__device__ __forceinline__ void mma16816(float& c0, float& c1, float& c2, float& c3,
                                         uint32_t a0, uint32_t a1, uint32_t a2, uint32_t a3,
                                         uint32_t b0, uint32_t b1) {
    asm volatile(
        "mma.sync.aligned.m16n8k16.row.col.f32.f16.f16.f32 "
        "{%0,%1,%2,%3}, {%4,%5,%6,%7}, {%8,%9}, {%0,%1,%2,%3};"
        : "+f"(c0), "+f"(c1), "+f"(c2), "+f"(c3)
        : "r"(a0), "r"(a1), "r"(a2), "r"(a3), "r"(b0), "r"(b1));
}

// ===================== kernel 1: pack weights to fp16 =====================
// g_Wh[o, 0:1024] = base_weight[o,:]; g_Wh[o, 1024 + i*8 + g] = spline_weight[o,i,g]
__global__ void kan_wpack(const float* __restrict__ bw, const float* __restrict__ sw) {
    constexpr int HK = NK / 2;                       // 4608 fp16-pairs per output row
    int p = blockIdx.x * blockDim.x + threadIdx.x;   // exact grid
    int o  = p / HK;
    int r  = p - o * HK;
    int kk = r * 2;
    float2 f;
    if (kk < NIN)
        f = *reinterpret_cast<const float2*>(bw + (size_t)o * NIN + kk);
    else
        f = *reinterpret_cast<const float2*>(sw + (size_t)o * (NIN * COEF) + (kk - NIN));
    reinterpret_cast<__half2*>(g_Wh + (size_t)o * NK)[r] = __floats2half2_rn(f.x, f.y);
}

// ===================== kernel 2: activations (silu + cubic B-spline bases) =====================
__global__ void kan_act(const float* __restrict__ x) {
    int idx = blockIdx.x * blockDim.x + threadIdx.x;   // exact grid
    int b = idx >> 10;
    int i = idx & (NIN - 1);
    float v = x[idx];
    size_t ro = (size_t)b * NK;

    // silu
    float s = v / (1.0f + __expf(-v));
    g_Ah[ro + i] = __float2half_rn(s);

    // uniform cubic B-spline on knots (i-3)/5: interval j = floor(5x) in [0,4], t in [0,1)
    float xs = v * 5.0f;
    int j = (int)floorf(xs);
    j = (j < 0) ? 0 : ((j > 4) ? 4 : j);
    float t = xs - (float)j;
    float t2 = t * t, t3 = t2 * t, omt = 1.0f - t;
    float n0 = omt * omt * omt * (1.0f / 6.0f);
    float n1 = (3.0f * t3 - 6.0f * t2 + 4.0f) * (1.0f / 6.0f);
    float n2 = (-3.0f * t3 + 3.0f * t2 + 3.0f * t + 1.0f) * (1.0f / 6.0f);
    float n3 = t3 * (1.0f / 6.0f);

    __half h[8];
#pragma unroll
    for (int g = 0; g < 8; ++g) {
        float val = (g == j) ? n0 : (g == j + 1) ? n1 : (g == j + 2) ? n2
                  : (g == j + 3) ? n3 : 0.0f;
        h[g] = __float2half_rn(val);
    }
    __half2 p0 = __halves2half2(h[0], h[1]);
    __half2 p1 = __halves2half2(h[2], h[3]);
    __half2 p2 = __halves2half2(h[4], h[5]);
    __half2 p3 = __halves2half2(h[6], h[7]);
    uint4 u;
    u.x = *reinterpret_cast<uint32_t*>(&p0);
    u.y = *reinterpret_cast<uint32_t*>(&p1);
    u.z = *reinterpret_cast<uint32_t*>(&p2);
    u.w = *reinterpret_cast<uint32_t*>(&p3);
    *reinterpret_cast<uint4*>(g_Ah + ro + NIN + (size_t)i * 8) = u;  // 16B aligned
}

// ===================== kernel 3: pipelined HMMA GEMM (256x128x64, 64x64 warp tiles) ====
// out[m,n] = sum_k A[m,k] * W[n,k].  smem rows of 64 halves = 8 chunks of 16B,
// chunk swizzle: phys = c ^ (row & 7).
__global__ void __launch_bounds__(256, 1) kan_gemm(float* __restrict__ out) {
    extern __shared__ __align__(1024) char smem[];
    const uint32_t sb = smem_u32(smem);
    const uint32_t sbA = sb;
    const uint32_t sbB = sb + STAGES * A_TILE;

    const int tid = threadIdx.x;
    const int lane = tid & 31;
    const int wid = tid >> 5;
    const int wm = wid & 3;          // 4 warps along M (64 rows each)
    const int wn = wid >> 2;         // 2 warps along N (64 cols each)

    const int ntile = blockIdx.x & 7;        // n fastest: A-tile L2 reuse
    const int mtile = blockIdx.x >> 3;
    const int m0 = mtile * BM;
    const int n0 = ntile * BN;

    const char* gA = (const char*)(g_Ah) + ((size_t)m0 * NK) * 2;
    const char* gB = (const char*)(g_Wh) + ((size_t)n0 * NK) * 2;

    // A: 2048 16B-chunks/stage (8 per thread); B: 1024 (4 per thread)
    auto load_stage = [&](int s, int kt) {
        const uint32_t dA = sbA + (uint32_t)s * A_TILE;
        const uint32_t dB = sbB + (uint32_t)s * B_TILE;
        const size_t koff = (size_t)kt * BK * 2;
#pragma unroll
        for (int i = 0; i < 8; ++i) {
            int c = tid + i * 256;
            int row = c >> 3, col = c & 7;
            uint32_t doff = ((uint32_t)(row << 3) + (uint32_t)(col ^ (row & 7))) << 4;
            cp16(dA + doff, gA + (size_t)row * (NK * 2) + koff + (size_t)col * 16);
        }
#pragma unroll
        for (int i = 0; i < 4; ++i) {
            int c = tid + i * 256;
            int row = c >> 3, col = c & 7;
            uint32_t doff = ((uint32_t)(row << 3) + (uint32_t)(col ^ (row & 7))) << 4;
            cp16(dB + doff, gB + (size_t)row * (NK * 2) + koff + (size_t)col * 16);
        }
    };

    // ---- prologue: 2 stages in flight ----
    load_stage(0, 0); CP_COMMIT();
    load_stage(1, 1); CP_COMMIT();

    float acc[4][8][4];
#pragma unroll
    for (int mi = 0; mi < 4; ++mi)
#pragma unroll
        for (int ni = 0; ni < 8; ++ni)
#pragma unroll
            for (int r = 0; r < 4; ++r) acc[mi][ni][r] = 0.0f;

    // ldmatrix lane addressing
    const int arow = wm * 64 + (lane & 15);
    const int brow = wn * 64 + (lane & 7) + ((lane >> 4) << 3);
    const uint32_t aPar  = (uint32_t)(arow & 7);
    const uint32_t bPar  = (uint32_t)(brow & 7);
    const uint32_t aKsel = (uint32_t)(lane >> 4);
    const uint32_t bKsel = (uint32_t)((lane >> 3) & 1);
    const uint32_t aRowOff = (uint32_t)arow << 7;   // row * 128B
    const uint32_t bRowOff = (uint32_t)brow << 7;

    int s = 0;          // stage being computed
    int sl = 2;         // stage to load into
    for (int kt = 0; kt < KTILES; ++kt) {
        CP_WAIT1();                 // group kt complete -> stage s resident
        __syncthreads();            // and everyone finished reading stage sl (last iter's s-1)

        if (kt + 2 < KTILES) load_stage(sl, kt + 2);
        CP_COMMIT();                // empty groups at the tail keep accounting uniform

        const uint32_t tA = sbA + (uint32_t)s * A_TILE;
        const uint32_t tB = sbB + (uint32_t)s * B_TILE;
#pragma unroll
        for (int ks = 0; ks < 4; ++ks) {
            uint32_t a[4][4];
            const uint32_t aChunk = (((uint32_t)(ks * 2) + aKsel) ^ aPar) << 4;
#pragma unroll
            for (int mi = 0; mi < 4; ++mi)     // +16 rows = +2048B
                ldmx4(a[mi][0], a[mi][1], a[mi][2], a[mi][3],
                      tA + aRowOff + ((uint32_t)mi << 11) + aChunk);
            uint32_t b[8][2];
            const uint32_t bChunk = (((uint32_t)(ks * 2) + bKsel) ^ bPar) << 4;
#pragma unroll
            for (int g = 0; g < 4; ++g) {
                uint32_t q0, q1, q2, q3;
                ldmx4(q0, q1, q2, q3, tB + bRowOff + ((uint32_t)g << 11) + bChunk);
                b[g * 2 + 0][0] = q0; b[g * 2 + 0][1] = q1;
                b[g * 2 + 1][0] = q2; b[g * 2 + 1][1] = q3;
            }
#pragma unroll
            for (int mi = 0; mi < 4; ++mi)
#pragma unroll
                for (int ni = 0; ni < 8; ++ni)
                    mma16816(acc[mi][ni][0], acc[mi][ni][1], acc[mi][ni][2], acc[mi][ni][3],
                             a[mi][0], a[mi][1], a[mi][2], a[mi][3],
                             b[ni][0], b[ni][1]);
        }

        if (++s == STAGES) s = 0;
        if (++sl == STAGES) sl = 0;
    }

    // ---- epilogue ----
    const int q = lane >> 2, p = lane & 3;
#pragma unroll
    for (int mi = 0; mi < 4; ++mi) {
        int mbase = m0 + wm * 64 + mi * 16 + q;
#pragma unroll
        for (int ni = 0; ni < 8; ++ni) {
            int nbase = n0 + wn * 64 + ni * 8 + p * 2;
            *reinterpret_cast<float2*>(out + (size_t)mbase * NOUT + nbase) =
                make_float2(acc[mi][ni][0], acc[mi][ni][1]);
            *reinterpret_cast<float2*>(out + (size_t)(mbase + 8) * NOUT + nbase) =
                make_float2(acc[mi][ni][2], acc[mi][ni][3]);
        }
    }
}

// ===================== host launcher =====================
extern "C" void kernel_launch(void* const* d_in, const int* in_sizes, int n_in,
                              void* d_out, int out_size) {
    const float* x  = (const float*)d_in[0];
    const float* bw = (const float*)d_in[1];
    const float* sw = (const float*)d_in[2];
    float* out = (float*)d_out;

    cudaFuncSetAttribute(kan_gemm, cudaFuncAttributeMaxDynamicSharedMemorySize,
                         (int)SMEM_TOTAL);

    kan_wpack<<<(NOUT * (NK / 2)) / 256, 256>>>(bw, sw);
    kan_act<<<(NB * NIN) / 256, 256>>>(x);
    kan_gemm<<<(NB / BM) * (NOUT / BN), 256, SMEM_TOTAL>>>(out);
}

// round 5
// speedup vs baseline: 1.2022x; 1.0249x over previous
#include <cuda_runtime.h>
#include <cuda_fp16.h>
#include <cstdint>
#include <cstddef>

// ===================== problem constants =====================
static constexpr int NB   = 8192;               // batch
static constexpr int NIN  = 1024;               // in features
static constexpr int NOUT = 1024;               // out features
static constexpr int COEF = 8;                  // grid_size + spline_order
static constexpr int NK   = NIN + NIN * COEF;   // 9216 fused K

// ===================== gemm tiling =====================
static constexpr int BM = 256;
static constexpr int BN = 128;
static constexpr int BK = 64;                   // 64 fp16 = 128B rows in smem
static constexpr int KTILES = NK / BK;          // 144
static constexpr int STAGES = 4;                // power of two

static constexpr uint32_t A_TILE = (uint32_t)BM * BK * 2;          // 32768
static constexpr uint32_t B_TILE = (uint32_t)BN * BK * 2;          // 16384
static constexpr uint32_t SMEM_TOTAL = STAGES * (A_TILE + B_TILE); // 196608

// ===================== device scratch (no allocations allowed) =====================
__device__ __align__(1024) __half g_Ah[(size_t)NB * NK];     // ~151 MB fp16 activations
__device__ __align__(1024) __half g_Wh[(size_t)NOUT * NK];   // ~19 MB fp16 packed weights

// ===================== helpers =====================
__device__ __forceinline__ uint32_t smem_u32(const void* p) {
    uint32_t a;
    asm("{ .reg .u64 t; cvta.to.shared.u64 t, %1; cvt.u32.u64 %0, t; }" : "=r"(a) : "l"(p));
    return a;
}
__device__ __forceinline__ void cp16(uint32_t dst, const void* src) {
    asm volatile("cp.async.cg.shared.global [%0], [%1], 16;" :: "r"(dst), "l"(src) : "memory");
}
#define CP_COMMIT() asm volatile("cp.async.commit_group;" ::: "memory")
#define CP_WAIT2()  asm volatile("cp.async.wait_group 2;" ::: "memory")

__device__ __forceinline__ void ldmx4(uint32_t& r0, uint32_t& r1, uint32_t& r2, uint32_t& r3,
                                      uint32_t addr) {
    asm volatile("ldmatrix.sync.aligned.m8n8.x4.shared.b16 {%0,%1,%2,%3}, [%4];"
                 : "=r"(r0), "=r"(r1), "=r"(r2), "=r"(r3) : "r"(addr));
}
__device__ __forceinline__ void mma16816(float& c0, float& c1, float& c2, float& c3,
                                         uint32_t a0, uint32_t a1, uint32_t a2, uint32_t a3,
                                         uint32_t b0, uint32_t b1) {
    asm volatile(
        "mma.sync.aligned.m16n8k16.row.col.f32.f16.f16.f32 "
        "{%0,%1,%2,%3}, {%4,%5,%6,%7}, {%8,%9}, {%0,%1,%2,%3};"
        : "+f"(c0), "+f"(c1), "+f"(c2), "+f"(c3)
        : "r"(a0), "r"(a1), "r"(a2), "r"(a3), "r"(b0), "r"(b1));
}

// ===================== kernel 1: fused prep (weight pack + activations) =====================
static constexpr int WPACK_BLOCKS = (NOUT * (NK / 2)) / 256;   // 18432
static constexpr int ACT_BLOCKS   = (NB * NIN) / 256;          // 32768

__global__ void kan_prep(const float* __restrict__ x,
                         const float* __restrict__ bw,
                         const float* __restrict__ sw) {
    if (blockIdx.x < WPACK_BLOCKS) {
        // ---- pack weights: g_Wh[o,0:1024]=bw[o,:]; g_Wh[o,1024+i*8+g]=sw[o,i,g] ----
        constexpr int HK = NK / 2;
        int p = blockIdx.x * blockDim.x + threadIdx.x;
        int o  = p / HK;
        int r  = p - o * HK;
        int kk = r * 2;
        float2 f;
        if (kk < NIN)
            f = *reinterpret_cast<const float2*>(bw + (size_t)o * NIN + kk);
        else
            f = *reinterpret_cast<const float2*>(sw + (size_t)o * (NIN * COEF) + (kk - NIN));
        reinterpret_cast<__half2*>(g_Wh + (size_t)o * NK)[r] = __floats2half2_rn(f.x, f.y);
        return;
    }
    // ---- activations: silu + closed-form uniform cubic B-spline bases ----
    int idx = (blockIdx.x - WPACK_BLOCKS) * blockDim.x + threadIdx.x;
    int b = idx >> 10;
    int i = idx & (NIN - 1);
    float v = x[idx];
    size_t ro = (size_t)b * NK;

    float s = v / (1.0f + __expf(-v));
    g_Ah[ro + i] = __float2half_rn(s);

    float xs = v * 5.0f;
    int j = (int)floorf(xs);
    j = (j < 0) ? 0 : ((j > 4) ? 4 : j);
    float t = xs - (float)j;
    float t2 = t * t, t3 = t2 * t, omt = 1.0f - t;
    float n0 = omt * omt * omt * (1.0f / 6.0f);
    float n1 = (3.0f * t3 - 6.0f * t2 + 4.0f) * (1.0f / 6.0f);
    float n2 = (-3.0f * t3 + 3.0f * t2 + 3.0f * t + 1.0f) * (1.0f / 6.0f);
    float n3 = t3 * (1.0f / 6.0f);

    __half h[8];
#pragma unroll
    for (int g = 0; g < 8; ++g) {
        float val = (g == j) ? n0 : (g == j + 1) ? n1 : (g == j + 2) ? n2
                  : (g == j + 3) ? n3 : 0.0f;
        h[g] = __float2half_rn(val);
    }
    __half2 p0 = __halves2half2(h[0], h[1]);
    __half2 p1 = __halves2half2(h[2], h[3]);
    __half2 p2 = __halves2half2(h[4], h[5]);
    __half2 p3 = __halves2half2(h[6], h[7]);
    uint4 u;
    u.x = *reinterpret_cast<uint32_t*>(&p0);
    u.y = *reinterpret_cast<uint32_t*>(&p1);
    u.z = *reinterpret_cast<uint32_t*>(&p2);
    u.w = *reinterpret_cast<uint32_t*>(&p3);
    *reinterpret_cast<uint4*>(g_Ah + ro + NIN + (size_t)i * 8) = u;
}

// ===================== kernel 2: pipelined HMMA GEMM =====================
// 256x128x64 CTA tile, 64x64 warp tiles, 4 smem stages, register double-buffered
// fragments. smem rows of 64 halves = 8 chunks of 16B, chunk swizzle phys = c ^ (row&7).
__global__ void __launch_bounds__(256, 1) kan_gemm(float* __restrict__ out) {
    extern __shared__ __align__(1024) char smem[];
    const uint32_t sb = smem_u32(smem);
    const uint32_t sbA = sb;
    const uint32_t sbB = sb + STAGES * A_TILE;

    const int tid = threadIdx.x;
    const int lane = tid & 31;
    const int wid = tid >> 5;
    const int wm = wid & 3;          // 4 warps along M (64 rows each)
    const int wn = wid >> 2;         // 2 warps along N (64 cols each)

    const int ntile = blockIdx.x & 7;        // n fastest: A-tile L2 reuse
    const int mtile = blockIdx.x >> 3;
    const int m0 = mtile * BM;
    const int n0 = ntile * BN;

    const char* gA = (const char*)(g_Ah) + ((size_t)m0 * NK) * 2;
    const char* gB = (const char*)(g_Wh) + ((size_t)n0 * NK) * 2;

    auto load_stage = [&](int s, int kt) {
        const uint32_t dA = sbA + (uint32_t)s * A_TILE;
        const uint32_t dB = sbB + (uint32_t)s * B_TILE;
        const size_t koff = (size_t)kt * BK * 2;
#pragma unroll
        for (int i = 0; i < 8; ++i) {
            int c = tid + i * 256;
            int row = c >> 3, col = c & 7;
            uint32_t doff = ((uint32_t)(row << 3) + (uint32_t)(col ^ (row & 7))) << 4;
            cp16(dA + doff, gA + (size_t)row * (NK * 2) + koff + (size_t)col * 16);
        }
#pragma unroll
        for (int i = 0; i < 4; ++i) {
            int c = tid + i * 256;
            int row = c >> 3, col = c & 7;
            uint32_t doff = ((uint32_t)(row << 3) + (uint32_t)(col ^ (row & 7))) << 4;
            cp16(dB + doff, gB + (size_t)row * (NK * 2) + koff + (size_t)col * 16);
        }
    };

    // ---- prologue: 3 stages in flight ----
    load_stage(0, 0); CP_COMMIT();
    load_stage(1, 1); CP_COMMIT();
    load_stage(2, 2); CP_COMMIT();

    float acc[4][8][4];
#pragma unroll
    for (int mi = 0; mi < 4; ++mi)
#pragma unroll
        for (int ni = 0; ni < 8; ++ni)
#pragma unroll
            for (int r = 0; r < 4; ++r) acc[mi][ni][r] = 0.0f;

    // ldmatrix lane addressing
    const int arow = wm * 64 + (lane & 15);
    const int brow = wn * 64 + (lane & 7) + ((lane >> 4) << 3);
    const uint32_t aPar  = (uint32_t)(arow & 7);
    const uint32_t bPar  = (uint32_t)(brow & 7);
    const uint32_t aKsel = (uint32_t)(lane >> 4);
    const uint32_t bKsel = (uint32_t)((lane >> 3) & 1);
    const uint32_t aBase = (uint32_t)arow << 7;   // row * 128B
    const uint32_t bBase = (uint32_t)brow << 7;

    uint32_t fa[2][4][4];    // [buf][mi][reg]
    uint32_t fb[2][8][2];    // [buf][ni][reg]

    auto load_frags = [&](int buf, uint32_t tA, uint32_t tB, int ks) {
        const uint32_t aChunk = (((uint32_t)(ks * 2) + aKsel) ^ aPar) << 4;
#pragma unroll
        for (int mi = 0; mi < 4; ++mi)
            ldmx4(fa[buf][mi][0], fa[buf][mi][1], fa[buf][mi][2], fa[buf][mi][3],
                  tA + aBase + ((uint32_t)mi << 11) + aChunk);
        const uint32_t bChunk = (((uint32_t)(ks * 2) + bKsel) ^ bPar) << 4;
#pragma unroll
        for (int g = 0; g < 4; ++g) {
            uint32_t q0, q1, q2, q3;
            ldmx4(q0, q1, q2, q3, tB + bBase + ((uint32_t)g << 11) + bChunk);
            fb[buf][g * 2 + 0][0] = q0; fb[buf][g * 2 + 0][1] = q1;
            fb[buf][g * 2 + 1][0] = q2; fb[buf][g * 2 + 1][1] = q3;
        }
    };
    auto mma_block = [&](int buf) {
#pragma unroll
        for (int mi = 0; mi < 4; ++mi)
#pragma unroll
            for (int ni = 0; ni < 8; ++ni)
                mma16816(acc[mi][ni][0], acc[mi][ni][1], acc[mi][ni][2], acc[mi][ni][3],
                         fa[buf][mi][0], fa[buf][mi][1], fa[buf][mi][2], fa[buf][mi][3],
                         fb[buf][ni][0], fb[buf][ni][1]);
    };

    for (int kt = 0; kt < KTILES; ++kt) {
        CP_WAIT2();                 // stage kt resident (<=2 groups in flight)
        __syncthreads();            // all warps done reading stage (kt-1)&3 == (kt+3)&3

        if (kt + 3 < KTILES) load_stage((kt + 3) & (STAGES - 1), kt + 3);
        CP_COMMIT();                // empty tail groups keep wait accounting uniform

        const uint32_t tA = sbA + (uint32_t)(kt & (STAGES - 1)) * A_TILE;
        const uint32_t tB = sbB + (uint32_t)(kt & (STAGES - 1)) * B_TILE;

        load_frags(0, tA, tB, 0);   // only exposed LDSM latency: once per K-tile
#pragma unroll
        for (int ks = 0; ks < 4; ++ks) {
            if (ks < 3) load_frags((ks + 1) & 1, tA, tB, ks + 1);  // prefetch during MMA
            mma_block(ks & 1);
        }
    }

    // ---- epilogue ----
    const int q = lane >> 2, p = lane & 3;
#pragma unroll
    for (int mi = 0; mi < 4; ++mi) {
        int mbase = m0 + wm * 64 + mi * 16 + q;
#pragma unroll
        for (int ni = 0; ni < 8; ++ni) {
            int nbase = n0 + wn * 64 + ni * 8 + p * 2;
            *reinterpret_cast<float2*>(out + (size_t)mbase * NOUT + nbase) =
                make_float2(acc[mi][ni][0], acc[mi][ni][1]);
            *reinterpret_cast<float2*>(out + (size_t)(mbase + 8) * NOUT + nbase) =
                make_float2(acc[mi][ni][2], acc[mi][ni][3]);
        }
    }
}

// ===================== host launcher =====================
extern "C" void kernel_launch(void* const* d_in, const int* in_sizes, int n_in,
                              void* d_out, int out_size) {
    const float* x  = (const float*)d_in[0];
    const float* bw = (const float*)d_in[1];
    const float* sw = (const float*)d_in[2];
    float* out = (float*)d_out;

    cudaFuncSetAttribute(kan_gemm, cudaFuncAttributeMaxDynamicSharedMemorySize,
                         (int)SMEM_TOTAL);

    kan_prep<<<WPACK_BLOCKS + ACT_BLOCKS, 256>>>(x, bw, sw);
    kan_gemm<<<(NB / BM) * (NOUT / BN), 256, SMEM_TOTAL>>>(out);
}

// round 6
// speedup vs baseline: 1.2499x; 1.0396x over previous
#include <cuda_runtime.h>
#include <cuda_fp16.h>
#include <cstdint>
#include <cstddef>

// ===================== problem constants =====================
static constexpr int NB   = 8192;               // batch
static constexpr int NIN  = 1024;               // in features
static constexpr int NOUT = 1024;               // out features
static constexpr int COEF = 8;                  // grid_size + spline_order
static constexpr int NK   = NIN + NIN * COEF;   // 9216 fused K

// ===================== gemm tiling =====================
static constexpr int BM = 256;
static constexpr int BN = 128;
static constexpr int BK = 128;                  // two 64-half sub-tiles per stage
static constexpr int KTILES = NK / BK;          // 72
static constexpr int STAGES = 2;

static constexpr uint32_t A_SUB  = (uint32_t)BM * 64 * 2;      // 32768
static constexpr uint32_t B_SUB  = (uint32_t)BN * 64 * 2;      // 16384
static constexpr uint32_t A_TILE = 2 * A_SUB;                  // 65536
static constexpr uint32_t B_TILE = 2 * B_SUB;                  // 32768
static constexpr uint32_t SMEM_TOTAL = STAGES * (A_TILE + B_TILE); // 196608

// ===================== device scratch (no allocations allowed) =====================
__device__ __align__(1024) __half g_Ah[(size_t)NB * NK];     // ~151 MB fp16 activations
__device__ __align__(1024) __half g_Wh[(size_t)NOUT * NK];   // ~19 MB fp16 packed weights

// ===================== helpers =====================
__device__ __forceinline__ uint32_t smem_u32(const void* p) {
    uint32_t a;
    asm("{ .reg .u64 t; cvta.to.shared.u64 t, %1; cvt.u32.u64 %0, t; }" : "=r"(a) : "l"(p));
    return a;
}
__device__ __forceinline__ void cp16(uint32_t dst, const void* src) {
    asm volatile("cp.async.cg.shared.global [%0], [%1], 16;" :: "r"(dst), "l"(src) : "memory");
}
#define CP_COMMIT() asm volatile("cp.async.commit_group;" ::: "memory")
#define CP_WAIT0()  asm volatile("cp.async.wait_group 0;" ::: "memory")

__device__ __forceinline__ void ldmx4(uint32_t& r0, uint32_t& r1, uint32_t& r2, uint32_t& r3,
                                      uint32_t addr) {
    asm volatile("ldmatrix.sync.aligned.m8n8.x4.shared.b16 {%0,%1,%2,%3}, [%4];"
                 : "=r"(r0), "=r"(r1), "=r"(r2), "=r"(r3) : "r"(addr));
}
__device__ __forceinline__ void mma16816(float& c0, float& c1, float& c2, float& c3,
                                         uint32_t a0, uint32_t a1, uint32_t a2, uint32_t a3,
                                         uint32_t b0, uint32_t b1) {
    asm volatile(
        "mma.sync.aligned.m16n8k16.row.col.f32.f16.f16.f32 "
        "{%0,%1,%2,%3}, {%4,%5,%6,%7}, {%8,%9}, {%0,%1,%2,%3};"
        : "+f"(c0), "+f"(c1), "+f"(c2), "+f"(c3)
        : "r"(a0), "r"(a1), "r"(a2), "r"(a3), "r"(b0), "r"(b1));
}

// ===================== kernel 1: fused prep (weight pack + activations) =====================
static constexpr int WPACK_BLOCKS = (NOUT * (NK / 2)) / 256;   // 18432
static constexpr int ACT_BLOCKS   = (NB * NIN) / 256;          // 32768

__global__ void kan_prep(const float* __restrict__ x,
                         const float* __restrict__ bw,
                         const float* __restrict__ sw) {
    if (blockIdx.x < WPACK_BLOCKS) {
        // ---- pack weights: g_Wh[o,0:1024]=bw[o,:]; g_Wh[o,1024+i*8+g]=sw[o,i,g] ----
        constexpr int HK = NK / 2;
        int p = blockIdx.x * blockDim.x + threadIdx.x;
        int o  = p / HK;
        int r  = p - o * HK;
        int kk = r * 2;
        float2 f;
        if (kk < NIN)
            f = *reinterpret_cast<const float2*>(bw + (size_t)o * NIN + kk);
        else
            f = *reinterpret_cast<const float2*>(sw + (size_t)o * (NIN * COEF) + (kk - NIN));
        reinterpret_cast<__half2*>(g_Wh + (size_t)o * NK)[r] = __floats2half2_rn(f.x, f.y);
        return;
    }
    // ---- activations: silu + closed-form uniform cubic B-spline bases ----
    int idx = (blockIdx.x - WPACK_BLOCKS) * blockDim.x + threadIdx.x;
    int b = idx >> 10;
    int i = idx & (NIN - 1);
    float v = x[idx];
    size_t ro = (size_t)b * NK;

    float s = v / (1.0f + __expf(-v));
    g_Ah[ro + i] = __float2half_rn(s);

    float xs = v * 5.0f;
    int j = (int)floorf(xs);
    j = (j < 0) ? 0 : ((j > 4) ? 4 : j);
    float t = xs - (float)j;
    float t2 = t * t, t3 = t2 * t, omt = 1.0f - t;
    float n0 = omt * omt * omt * (1.0f / 6.0f);
    float n1 = (3.0f * t3 - 6.0f * t2 + 4.0f) * (1.0f / 6.0f);
    float n2 = (-3.0f * t3 + 3.0f * t2 + 3.0f * t + 1.0f) * (1.0f / 6.0f);
    float n3 = t3 * (1.0f / 6.0f);

    __half h[8];
#pragma unroll
    for (int g = 0; g < 8; ++g) {
        float val = (g == j) ? n0 : (g == j + 1) ? n1 : (g == j + 2) ? n2
                  : (g == j + 3) ? n3 : 0.0f;
        h[g] = __float2half_rn(val);
    }
    __half2 p0 = __halves2half2(h[0], h[1]);
    __half2 p1 = __halves2half2(h[2], h[3]);
    __half2 p2 = __halves2half2(h[4], h[5]);
    __half2 p3 = __halves2half2(h[6], h[7]);
    uint4 u;
    u.x = *reinterpret_cast<uint32_t*>(&p0);
    u.y = *reinterpret_cast<uint32_t*>(&p1);
    u.z = *reinterpret_cast<uint32_t*>(&p2);
    u.w = *reinterpret_cast<uint32_t*>(&p3);
    *reinterpret_cast<uint4*>(g_Ah + ro + NIN + (size_t)i * 8) = u;
}

// ===================== kernel 2: pipelined HMMA GEMM =====================
// 256x128x128 CTA tile (two 64-wide sub-tiles), 64x64 warp tiles, 2 smem stages,
// register double-buffered fragments. Sub-tile rows = 64 halves = 8 chunks of 16B,
// chunk swizzle phys = c ^ (row & 7).
__global__ void __launch_bounds__(256, 1) kan_gemm(float* __restrict__ out) {
    extern __shared__ __align__(1024) char smem[];
    const uint32_t sb = smem_u32(smem);
    const uint32_t sbA = sb;
    const uint32_t sbB = sb + STAGES * A_TILE;

    const int tid = threadIdx.x;
    const int lane = tid & 31;
    const int wid = tid >> 5;
    const int wm = wid & 3;          // 4 warps along M (64 rows each)
    const int wn = wid >> 2;         // 2 warps along N (64 cols each)

    const int ntile = blockIdx.x & 7;        // n fastest: A-tile L2 reuse
    const int mtile = blockIdx.x >> 3;
    const int m0 = mtile * BM;
    const int n0 = ntile * BN;

    const char* gA = (const char*)(g_Ah) + ((size_t)m0 * NK) * 2;
    const char* gB = (const char*)(g_Wh) + ((size_t)n0 * NK) * 2;

    // stage = [sub0 | sub1]; chunk c: row = c>>4, col = c&15, sub = col>>3
    auto load_stage = [&](int s, int kt) {
        const uint32_t dA = sbA + (uint32_t)s * A_TILE;
        const uint32_t dB = sbB + (uint32_t)s * B_TILE;
        const size_t koff = (size_t)kt * BK * 2;          // 256B per K-tile
#pragma unroll
        for (int i = 0; i < 16; ++i) {                    // A: 4096 chunks
            int c = tid + i * 256;
            int row = c >> 4, col = c & 15;
            uint32_t doff = (uint32_t)(col >> 3) * A_SUB + ((uint32_t)row << 7)
                          + (((uint32_t)(col & 7) ^ (uint32_t)(row & 7)) << 4);
            cp16(dA + doff, gA + (size_t)row * (NK * 2) + koff + (size_t)col * 16);
        }
#pragma unroll
        for (int i = 0; i < 8; ++i) {                     // B: 2048 chunks
            int c = tid + i * 256;
            int row = c >> 4, col = c & 15;
            uint32_t doff = (uint32_t)(col >> 3) * B_SUB + ((uint32_t)row << 7)
                          + (((uint32_t)(col & 7) ^ (uint32_t)(row & 7)) << 4);
            cp16(dB + doff, gB + (size_t)row * (NK * 2) + koff + (size_t)col * 16);
        }
    };

    // ---- prologue ----
    load_stage(0, 0); CP_COMMIT();

    float acc[4][8][4];
#pragma unroll
    for (int mi = 0; mi < 4; ++mi)
#pragma unroll
        for (int ni = 0; ni < 8; ++ni)
#pragma unroll
            for (int r = 0; r < 4; ++r) acc[mi][ni][r] = 0.0f;

    // ldmatrix lane addressing (within a 64-half sub-tile)
    const int arow = wm * 64 + (lane & 15);
    const int brow = wn * 64 + (lane & 7) + ((lane >> 4) << 3);
    const uint32_t aPar  = (uint32_t)(arow & 7);
    const uint32_t bPar  = (uint32_t)(brow & 7);
    const uint32_t aKsel = (uint32_t)(lane >> 4);
    const uint32_t bKsel = (uint32_t)((lane >> 3) & 1);
    const uint32_t aBase = (uint32_t)arow << 7;   // row * 128B
    const uint32_t bBase = (uint32_t)brow << 7;

    uint32_t fa[2][4][4];    // [buf][mi][reg]
    uint32_t fb[2][8][2];    // [buf][ni][reg]

    auto load_frags = [&](int buf, uint32_t tAs, uint32_t tBs, int ks) {
        const uint32_t aChunk = (((uint32_t)(ks * 2) + aKsel) ^ aPar) << 4;
#pragma unroll
        for (int mi = 0; mi < 4; ++mi)
            ldmx4(fa[buf][mi][0], fa[buf][mi][1], fa[buf][mi][2], fa[buf][mi][3],
                  tAs + aBase + ((uint32_t)mi << 11) + aChunk);
        const uint32_t bChunk = (((uint32_t)(ks * 2) + bKsel) ^ bPar) << 4;
#pragma unroll
        for (int g = 0; g < 4; ++g) {
            uint32_t q0, q1, q2, q3;
            ldmx4(q0, q1, q2, q3, tBs + bBase + ((uint32_t)g << 11) + bChunk);
            fb[buf][g * 2 + 0][0] = q0; fb[buf][g * 2 + 0][1] = q1;
            fb[buf][g * 2 + 1][0] = q2; fb[buf][g * 2 + 1][1] = q3;
        }
    };
    auto mma_block = [&](int buf) {
#pragma unroll
        for (int mi = 0; mi < 4; ++mi)
#pragma unroll
            for (int ni = 0; ni < 8; ++ni)
                mma16816(acc[mi][ni][0], acc[mi][ni][1], acc[mi][ni][2], acc[mi][ni][3],
                         fa[buf][mi][0], fa[buf][mi][1], fa[buf][mi][2], fa[buf][mi][3],
                         fb[buf][ni][0], fb[buf][ni][1]);
    };

    for (int kt = 0; kt < KTILES; ++kt) {
        CP_WAIT0();                 // stage kt&1 resident (issued last iteration)
        __syncthreads();            // all warps done reading stage (kt+1)&1

        if (kt + 1 < KTILES) { load_stage((kt + 1) & 1, kt + 1); CP_COMMIT(); }

        const uint32_t tA = sbA + (uint32_t)(kt & 1) * A_TILE;
        const uint32_t tB = sbB + (uint32_t)(kt & 1) * B_TILE;

        load_frags(0, tA, tB, 0);
#pragma unroll
        for (int k8 = 0; k8 < 8; ++k8) {      // 8 ks-steps across the two sub-tiles
            const int nk = k8 + 1;
            if (nk < 8)
                load_frags(nk & 1,
                           tA + (uint32_t)(nk >> 2) * A_SUB,
                           tB + (uint32_t)(nk >> 2) * B_SUB,
                           nk & 3);
            mma_block(k8 & 1);
        }
    }

    // ---- epilogue ----
    const int q = lane >> 2, p = lane & 3;
#pragma unroll
    for (int mi = 0; mi < 4; ++mi) {
        int mbase = m0 + wm * 64 + mi * 16 + q;
#pragma unroll
        for (int ni = 0; ni < 8; ++ni) {
            int nbase = n0 + wn * 64 + ni * 8 + p * 2;
            *reinterpret_cast<float2*>(out + (size_t)mbase * NOUT + nbase) =
                make_float2(acc[mi][ni][0], acc[mi][ni][1]);
            *reinterpret_cast<float2*>(out + (size_t)(mbase + 8) * NOUT + nbase) =
                make_float2(acc[mi][ni][2], acc[mi][ni][3]);
        }
    }
}

// ===================== host launcher =====================
extern "C" void kernel_launch(void* const* d_in, const int* in_sizes, int n_in,
                              void* d_out, int out_size) {
    const float* x  = (const float*)d_in[0];
    const float* bw = (const float*)d_in[1];
    const float* sw = (const float*)d_in[2];
    float* out = (float*)d_out;

    cudaFuncSetAttribute(kan_gemm, cudaFuncAttributeMaxDynamicSharedMemorySize,
                         (int)SMEM_TOTAL);

    kan_prep<<<WPACK_BLOCKS + ACT_BLOCKS, 256>>>(x, bw, sw);
    kan_gemm<<<(NB / BM) * (NOUT / BN), 256, SMEM_TOTAL>>>(out);
}